// round 9
// baseline (speedup 1.0000x reference)
#include <cuda_runtime.h>
#include <cstdint>

// Problem constants (fixed shapes per reference)
#define NNODES   30000
#define RREL     8
#define NBASES   30
#define IN_DIM   256
#define Z_DIM    128
#define HID      256           // Z_DIM*2
#define NEDGES   480000        // N*16
#define NSEG     (NNODES*RREL) // 240000
#define KAGG     (RREL*256)    // 2048

// ---------------- scratch (device globals; referenced DIRECTLY by kernels) ---
__device__ __align__(16) float g_M  [(size_t)NNODES * RREL * 256];  // 245.76 MB
__device__ __align__(16) float g_Z1 [(size_t)NNODES * HID];
__device__ __align__(16) float g_W1 [(size_t)RREL * IN_DIM * HID];  // [2048, 256]
__device__ __align__(16) float g_W2 [(size_t)RREL * HID * Z_DIM];   // [2048, 128]
__device__ __align__(16) float g_inv[NSEG];
__device__ int   g_cnt[NSEG];
__device__ int   g_src[NEDGES];
__device__ int   g_seg[NEDGES];
__device__ int   g_is64;

// ---------------- dtype autodetect (int32 vs int64 edge arrays) --------------
// int64 data: odd 32-bit words all zero, even words < RREL.
// int32 data: odd words are edge_type values, all-zero prob ~ 8^-64.
__global__ void detect_dtype(const unsigned* __restrict__ et_words) {
    int is64 = 1;
    for (int i = 0; i < 64; ++i) {
        unsigned lo = et_words[2 * i];
        unsigned hi = et_words[2 * i + 1];
        if (hi != 0u || lo >= (unsigned)RREL) { is64 = 0; break; }
    }
    g_is64 = is64;
}

// ---------------- utility kernels --------------------------------------------
__global__ void zero_M(int also_cnt) {
    size_t i = (size_t)blockIdx.x * 256 + threadIdx.x;
    size_t n4 = (size_t)NNODES * RREL * 64;
    if (i < n4) ((float4*)g_M)[i] = make_float4(0.f, 0.f, 0.f, 0.f);
    if (also_cnt && i < NSEG) g_cnt[i] = 0;
}

// edges -> int32 src/seg (dtype-agnostic), count edges per (dst, rel) segment.
// Indices clamped so a wrong branch fails correctness, never traps.
__global__ void prep_edges(const void* __restrict__ ei_raw,
                           const void* __restrict__ et_raw) {
    int e = blockIdx.x * 256 + threadIdx.x;
    if (e >= NEDGES) return;
    int s, d, t;
    if (g_is64) {
        const long long* ei = (const long long*)ei_raw;
        const long long* et = (const long long*)et_raw;
        s = (int)ei[e]; d = (int)ei[NEDGES + e]; t = (int)et[e];
    } else {
        const int* ei = (const int*)ei_raw;
        const int* et = (const int*)et_raw;
        s = ei[e];      d = ei[NEDGES + e];      t = et[e];
    }
    s = min(max(s, 0), NNODES - 1);
    d = min(max(d, 0), NNODES - 1);
    t = min(max(t, 0), RREL - 1);
    g_src[e] = s;
    int g = d * RREL + t;
    g_seg[e] = g;
    atomicAdd(&g_cnt[g], 1);
}

__global__ void make_inv() {
    int i = blockIdx.x * 256 + threadIdx.x;
    if (i < NSEG) g_inv[i] = 1.0f / fmaxf((float)g_cnt[i], 1.0f);
}

// W[r, io] = sum_b comp[r,b] * bases[b, io]   (layer selects g_W1/g_W2)
__global__ void build_W(const float* __restrict__ bases,
                        const float* __restrict__ comp,
                        int IO, int layer) {
    float* W = (layer == 1) ? g_W1 : g_W2;
    __shared__ float sc[RREL * NBASES];
    if (threadIdx.x < RREL * NBASES) sc[threadIdx.x] = comp[threadIdx.x];
    __syncthreads();
    int io = blockIdx.x * 256 + threadIdx.x;
    if (io >= IO) return;
    float acc[RREL];
#pragma unroll
    for (int r = 0; r < RREL; ++r) acc[r] = 0.f;
#pragma unroll 5
    for (int b = 0; b < NBASES; ++b) {
        float bv = bases[(size_t)b * IO + io];
#pragma unroll
        for (int r = 0; r < RREL; ++r) acc[r] += sc[r * NBASES + b] * bv;
    }
#pragma unroll
    for (int r = 0; r < RREL; ++r) W[(size_t)r * IO + io] = acc[r];
}

// g_M[seg[e], :] += inv[seg[e]] * feat[src[e], :]
__global__ void scatter_edges(const float* __restrict__ x, int use_z1) {
    const float* feat = use_z1 ? g_Z1 : x;
    int e = blockIdx.x * 4 + (threadIdx.x >> 6);
    int lane = threadIdx.x & 63;
    if (e >= NEDGES) return;
    int sg = g_seg[e];
    float sc = g_inv[sg];
    float4 v = *(const float4*)(feat + (size_t)g_src[e] * 256 + lane * 4);
    float* dst = g_M + (size_t)sg * 256 + lane * 4;
    atomicAdd(dst + 0, v.x * sc);
    atomicAdd(dst + 1, v.y * sc);
    atomicAdd(dst + 2, v.z * sc);
    atomicAdd(dst + 3, v.w * sc);
}

// ---------------- fused dual-GEMM + bias + optional leaky-relu ---------------
// C[n,:] = g_M[n,:2048] @ W[2048,ncols] + A2[n,:256] @ root[256,ncols] + bias
#define BM 128
#define BN 128
#define BK 16
#define TM 8
#define TN 8

__global__ __launch_bounds__(256, 2)
void gemm_fused(int layer, const float* __restrict__ xin,
                const float* __restrict__ root, const float* __restrict__ bias,
                float* __restrict__ outp, int ncols)
{
    __shared__ float sA[BK][BM + 4];
    __shared__ float sB[BK][BN];

    const float* B1 = (layer == 1) ? g_W1 : g_W2;
    const float* A2 = (layer == 1) ? xin  : g_Z1;
    float*       C  = (layer == 1) ? g_Z1 : outp;
    const int leaky = (layer == 1);

    int tid = threadIdx.x;
    int tx = tid & 15;
    int ty = tid >> 4;
    int row0 = blockIdx.x * BM;
    int col0 = blockIdx.y * BN;

    float acc[TM][TN];
#pragma unroll
    for (int i = 0; i < TM; ++i)
#pragma unroll
        for (int j = 0; j < TN; ++j) acc[i][j] = 0.f;

    for (int phase = 0; phase < 2; ++phase) {
        const float* A = phase ? A2 : g_M;
        const float* B = phase ? root : B1;
        int K = phase ? 256 : KAGG;

        for (int k0 = 0; k0 < K; k0 += BK) {
#pragma unroll
            for (int i = 0; i < 2; ++i) {
                int idx = tid + i * 256;          // 0..511
                int ar  = idx >> 2;               // 0..127
                int ac  = (idx & 3) * 4;          // 0,4,8,12
                int grow = row0 + ar;
                float4 v = make_float4(0.f, 0.f, 0.f, 0.f);
                if (grow < NNODES)
                    v = *(const float4*)&A[(size_t)grow * K + k0 + ac];
                sA[ac + 0][ar] = v.x;
                sA[ac + 1][ar] = v.y;
                sA[ac + 2][ar] = v.z;
                sA[ac + 3][ar] = v.w;
            }
#pragma unroll
            for (int i = 0; i < 2; ++i) {
                int idx = tid + i * 256;
                int bk  = idx >> 5;               // 0..15
                int bc  = (idx & 31) * 4;         // 0..124
                *(float4*)&sB[bk][bc] =
                    *(const float4*)&B[(size_t)(k0 + bk) * ncols + col0 + bc];
            }
            __syncthreads();

#pragma unroll
            for (int k = 0; k < BK; ++k) {
                float4 a0 = *(const float4*)&sA[k][ty * TM];
                float4 a1 = *(const float4*)&sA[k][ty * TM + 4];
                float4 b0 = *(const float4*)&sB[k][tx * TN];
                float4 b1 = *(const float4*)&sB[k][tx * TN + 4];
                float ra[TM] = {a0.x, a0.y, a0.z, a0.w, a1.x, a1.y, a1.z, a1.w};
                float rb[TN] = {b0.x, b0.y, b0.z, b0.w, b1.x, b1.y, b1.z, b1.w};
#pragma unroll
                for (int i = 0; i < TM; ++i)
#pragma unroll
                    for (int j = 0; j < TN; ++j)
                        acc[i][j] += ra[i] * rb[j];
            }
            __syncthreads();
        }
    }

#pragma unroll
    for (int i = 0; i < TM; ++i) {
        int r = row0 + ty * TM + i;
        if (r >= NNODES) continue;
#pragma unroll
        for (int j = 0; j < TN; j += 4) {
            int c = col0 + tx * TN + j;
            float4 o;
            o.x = acc[i][j + 0] + bias[c + 0];
            o.y = acc[i][j + 1] + bias[c + 1];
            o.z = acc[i][j + 2] + bias[c + 2];
            o.w = acc[i][j + 3] + bias[c + 3];
            if (leaky) {
                o.x = o.x > 0.f ? o.x : 0.01f * o.x;
                o.y = o.y > 0.f ? o.y : 0.01f * o.y;
                o.z = o.z > 0.f ? o.z : 0.01f * o.z;
                o.w = o.w > 0.f ? o.w : 0.01f * o.w;
            }
            *(float4*)&C[(size_t)r * ncols + c] = o;
        }
    }
}

// ---------------- host: robust input binding by element count ----------------
static const void* find_in(void* const* d_in, const int* sz, int n_in,
                           int want, int occ, int fallback_idx) {
    int seen = 0;
    for (int i = 0; i < n_in; ++i) {
        if (sz[i] == want) {
            if (seen == occ) return d_in[i];
            ++seen;
        }
    }
    return d_in[fallback_idx];
}

extern "C" void kernel_launch(void* const* d_in, const int* in_sizes, int n_in,
                              void* d_out, int out_size) {
    const float* x      = (const float*)find_in(d_in, in_sizes, n_in, NNODES * IN_DIM,       0, 0);
    const void*  ei     =               find_in(d_in, in_sizes, n_in, 2 * NEDGES,            0, 1);
    const void*  et     =               find_in(d_in, in_sizes, n_in, NEDGES,                0, 2);
    const float* bases1 = (const float*)find_in(d_in, in_sizes, n_in, NBASES * IN_DIM * HID, 0, 3);
    const float* comp1  = (const float*)find_in(d_in, in_sizes, n_in, RREL * NBASES,         0, 4);
    const float* root1  = (const float*)find_in(d_in, in_sizes, n_in, IN_DIM * HID,          0, 5);
    const float* bias1  = (const float*)find_in(d_in, in_sizes, n_in, HID,                   0, 6);
    const float* bases2 = (const float*)find_in(d_in, in_sizes, n_in, NBASES * HID * Z_DIM,  0, 7);
    const float* comp2  = (const float*)find_in(d_in, in_sizes, n_in, RREL * NBASES,         1, 8);
    const float* root2  = (const float*)find_in(d_in, in_sizes, n_in, HID * Z_DIM,           0, 9);
    const float* bias2  = (const float*)find_in(d_in, in_sizes, n_in, Z_DIM,                 0, 10);
    float* out = (float*)d_out;

    const int n4 = NNODES * RREL * 64;          // float4 count of g_M
    const int gZ = (n4 + 255) / 256;

    // prep
    detect_dtype<<<1, 1>>>((const unsigned*)et);
    zero_M<<<gZ, 256>>>(/*also_cnt=*/1);
    prep_edges<<<(NEDGES + 255) / 256, 256>>>(ei, et);
    make_inv<<<(NSEG + 255) / 256, 256>>>();
    build_W<<<(IN_DIM * HID + 255) / 256, 256>>>(bases1, comp1, IN_DIM * HID, 1);
    build_W<<<(HID * Z_DIM + 255) / 256, 256>>>(bases2, comp2, HID * Z_DIM, 2);

    // layer 1: M = scatter(x); Z1 = M@W1 + x@root1 + bias1; leaky
    scatter_edges<<<NEDGES / 4, 256>>>(x, /*use_z1=*/0);
    {
        dim3 grid((NNODES + BM - 1) / BM, HID / BN);
        gemm_fused<<<grid, 256>>>(1, x, root1, bias1, out, HID);
    }

    // layer 2: M = scatter(Z1); out = M@W2 + Z1@root2 + bias2
    zero_M<<<gZ, 256>>>(/*also_cnt=*/0);
    scatter_edges<<<NEDGES / 4, 256>>>(x, /*use_z1=*/1);
    {
        dim3 grid((NNODES + BM - 1) / BM, Z_DIM / BN);
        gemm_fused<<<grid, 256>>>(2, x, root2, bias2, out, Z_DIM);
    }
}